// round 1
// baseline (speedup 1.0000x reference)
#include <cuda_runtime.h>
#include <cstdint>

// Problem constants (fixed by the dataset)
#define NN   131072      // nodes
#define EE   1048576     // edges
#define HH   128         // hidden = emb dim
#define BBG  512         // graphs
#define PPG  32          // predicates per graph
#define NH   (NN*HH)     // 16,777,216 floats per [N,H] buffer

// ---------------- static device scratch (no runtime allocation) ----------------
__device__ float g_emb[NH];        // gathered embeddings / init-forward result
__device__ float g_h[NH];          // h0 / final h
__device__ float g_h2[NH];         // layer-0 output (prev)
__device__ float g_xinit[NH];      // input-proj additive term (bias + tail features)
__device__ float g_m[4ULL * NH];   // per-edge-type mailboxes (also agg0 for init at chunk 0)
__device__ float g_deg[NN];        // ne in-degree
__device__ float g_pool[BBG * HH];
__device__ float g_tp[BBG * HH];
__device__ float g_wbt[HH * HH];   // Wb transposed

// ---------------- helpers ----------------
__device__ __forceinline__ void red_add_v4(float* addr, float x, float y, float z, float w) {
    asm volatile("red.global.add.v4.f32 [%0], {%1,%2,%3,%4};"
                 :: "l"(addr), "f"(x), "f"(y), "f"(z), "f"(w) : "memory");
}

// ---------------- kernels ----------------

// emb = emb_table[global_id]
__global__ void k_gather(const float4* __restrict__ tab, const int* __restrict__ gid) {
    int idx = blockIdx.x * blockDim.x + threadIdx.x;   // over N*32 float4s
    if (idx >= NN * 32) return;
    int node = idx >> 5;
    int f    = idx & 31;
    ((float4*)g_emb)[idx] = tab[(size_t)gid[node] * 32 + f];
}

// one warp per edge; lanes cover the 128 floats as 32 float4s
__global__ void k_scatter(const float4* __restrict__ hsrc,
                          const int* __restrict__ src, const int* __restrict__ dst,
                          const int* __restrict__ et,  const float* __restrict__ norm,
                          int only_ne)
{
    int gw   = (blockIdx.x * blockDim.x + threadIdx.x) >> 5;
    int lane = threadIdx.x & 31;
    if (gw >= EE) return;
    int t = et[gw];
    if (only_ne && t != 0) return;
    float w = norm[gw];
    int s = src[gw], d = dst[gw];
    float4 v = hsrc[(size_t)s * 32 + lane];
    float* out = g_m + (only_ne ? (size_t)0 : (size_t)t * NH) + (size_t)d * HH + lane * 4;
    red_add_v4(out, v.x * w, v.y * w, v.z * w, v.w * w);
    if (only_ne && lane == 0) atomicAdd(&g_deg[d], 1.0f);
}

// init-forward select + precompute input-projection additive term
__global__ void k_select_xinit(const int* __restrict__ spo, const int* __restrict__ acc,
                               const int* __restrict__ pre, const float* __restrict__ Wt,
                               const float* __restrict__ bt)
{
    int idx = blockIdx.x * blockDim.x + threadIdx.x;   // over N*32 float4s
    if (idx >= NN * 32) return;
    int node = idx >> 5;
    int f    = idx & 31;
    int s0 = spo[node * 3 + 0];
    int s1 = spo[node * 3 + 1];
    int s2 = spo[node * 3 + 2];
    if ((s0 + s2) > 0 && g_deg[node] > 0.0f)
        ((float4*)g_emb)[idx] = ((const float4*)g_m)[idx];

    float coef[5];
    coef[0] = (float)s0; coef[1] = (float)s1; coef[2] = (float)s2;
    coef[3] = (float)acc[node]; coef[4] = (float)pre[node];
    float4 r = ((const float4*)bt)[f];
#pragma unroll
    for (int j = 0; j < 5; j++) {
        float4 w = ((const float4*)(Wt + (size_t)(128 + j) * HH))[f];
        r.x += coef[j] * w.x; r.y += coef[j] * w.y;
        r.z += coef[j] * w.z; r.w += coef[j] * w.w;
    }
    ((float4*)g_xinit)[idx] = r;
}

// C[N,128] = sum_ch A_ch[N,128] @ B_ch[128,128]  (+Cadd | +bias) (relu) (+resid)
__global__ void __launch_bounds__(256, 2) k_gemm(
    const float* __restrict__ A, long strideA,
    const float* __restrict__ Bm, long strideB, int nchunk,
    const float* __restrict__ Cadd, const float* __restrict__ bias,
    const float* __restrict__ resid, float* __restrict__ C, int do_relu)
{
    __shared__ float As[16][128];   // transposed: As[k][m]
    __shared__ float Bs[16][128];   // Bs[k][n]
    int tid  = threadIdx.x;
    int row0 = blockIdx.x * 128;
    int ty = tid >> 4, tx = tid & 15;

    float accv[8][8];
#pragma unroll
    for (int i = 0; i < 8; i++)
#pragma unroll
        for (int j = 0; j < 8; j++) accv[i][j] = 0.0f;

    int ar = tid >> 2, ac = (tid & 3) * 4;   // A loader: 64 rows x 4 float4-cols
    int br = tid >> 5, bc = (tid & 31) * 4;  // B loader: 8 rows  x 32 float4-cols

    int nkt = nchunk * 8;
    for (int kt = 0; kt < nkt; kt++) {
        int ch = kt >> 3;
        int kl = (kt & 7) * 16;
        const float* Ab = A  + (long)ch * strideA + kl;
        const float* Bb = Bm + (long)ch * strideB + (long)kl * HH;
#pragma unroll
        for (int rr = 0; rr < 2; rr++) {
            int r = ar + rr * 64;
            float4 va = *(const float4*)(Ab + (long)(row0 + r) * HH + ac);
            As[ac + 0][r] = va.x; As[ac + 1][r] = va.y;
            As[ac + 2][r] = va.z; As[ac + 3][r] = va.w;
        }
#pragma unroll
        for (int rr = 0; rr < 2; rr++) {
            int r = br + rr * 8;
            float4 vb = *(const float4*)(Bb + (long)r * HH + bc);
            *(float4*)&Bs[r][bc] = vb;
        }
        __syncthreads();
#pragma unroll
        for (int kk = 0; kk < 16; kk++) {
            float a[8], b[8];
            float4 t;
            t = *(const float4*)&As[kk][ty * 8];     a[0]=t.x; a[1]=t.y; a[2]=t.z; a[3]=t.w;
            t = *(const float4*)&As[kk][ty * 8 + 4]; a[4]=t.x; a[5]=t.y; a[6]=t.z; a[7]=t.w;
            t = *(const float4*)&Bs[kk][tx * 8];     b[0]=t.x; b[1]=t.y; b[2]=t.z; b[3]=t.w;
            t = *(const float4*)&Bs[kk][tx * 8 + 4]; b[4]=t.x; b[5]=t.y; b[6]=t.z; b[7]=t.w;
#pragma unroll
            for (int i = 0; i < 8; i++)
#pragma unroll
                for (int j = 0; j < 8; j++)
                    accv[i][j] += a[i] * b[j];
        }
        __syncthreads();
    }

#pragma unroll
    for (int i = 0; i < 8; i++) {
        long m    = row0 + ty * 8 + i;
        long base = m * HH + tx * 8;
#pragma unroll
        for (int j4 = 0; j4 < 2; j4++) {
            float4 v;
            v.x = accv[i][j4*4+0]; v.y = accv[i][j4*4+1];
            v.z = accv[i][j4*4+2]; v.w = accv[i][j4*4+3];
            if (Cadd) {
                float4 c = *(const float4*)(Cadd + base + j4*4);
                v.x += c.x; v.y += c.y; v.z += c.z; v.w += c.w;
            }
            if (bias) {
                float4 c = *(const float4*)(bias + tx*8 + j4*4);
                v.x += c.x; v.y += c.y; v.z += c.z; v.w += c.w;
            }
            if (do_relu) {
                v.x = fmaxf(v.x, 0.f); v.y = fmaxf(v.y, 0.f);
                v.z = fmaxf(v.z, 0.f); v.w = fmaxf(v.w, 0.f);
            }
            if (resid) {
                float4 c = *(const float4*)(resid + base + j4*4);
                v.x += c.x; v.y += c.y; v.z += c.z; v.w += c.w;
            }
            *(float4*)(C + base + j4*4) = v;
        }
    }
}

// Wb transpose (128x128)
__global__ void k_transpose(const float* __restrict__ Wb) {
    int idx = blockIdx.x * blockDim.x + threadIdx.x;   // 16384
    if (idx >= HH * HH) return;
    int r = idx >> 7, c = idx & 127;
    g_wbt[c * HH + r] = Wb[idx];
}

// segment-mean pool over predicate nodes
__global__ void k_pool(const float* __restrict__ h, const int* __restrict__ pred) {
    int b = blockIdx.x, j = threadIdx.x;   // 512 x 128
    float acc = 0.0f;
#pragma unroll 4
    for (int p = 0; p < PPG; p++) {
        int node = pred[b * PPG + p];
        acc += h[(size_t)node * HH + j];
    }
    g_pool[b * HH + j] = acc * (1.0f / PPG);
}

// tp[b] = Wb @ pool[b]
__global__ void k_tp() {
    int b = blockIdx.x, hrow = threadIdx.x;   // 512 x 128
    __shared__ float ps[HH];
    ps[hrow] = g_pool[b * HH + hrow];
    __syncthreads();
    float acc = 0.0f;
#pragma unroll 8
    for (int k = 0; k < HH; k++)
        acc += g_wbt[(size_t)k * HH + hrow] * ps[k];
    g_tp[b * HH + hrow] = acc;
}

// scores + per-graph log_softmax
__global__ void k_score(const float* __restrict__ h, const int* __restrict__ pred,
                        const float* __restrict__ bbp, float* __restrict__ out)
{
    int b = blockIdx.x;
    int tid = threadIdx.x;                 // 128 threads = 4 warps
    __shared__ __align__(16) float tps[HH];
    __shared__ float sc[PPG];
    tps[tid] = g_tp[b * HH + tid];
    __syncthreads();
    int warp = tid >> 5, lane = tid & 31;
    float4 tv = ((const float4*)tps)[lane];
    for (int p = warp; p < PPG; p += 4) {
        int node = pred[b * PPG + p];
        float4 hv = ((const float4*)h)[(size_t)node * 32 + lane];
        float d = hv.x * tv.x + hv.y * tv.y + hv.z * tv.z + hv.w * tv.w;
#pragma unroll
        for (int o = 16; o > 0; o >>= 1) d += __shfl_xor_sync(0xffffffffu, d, o);
        if (lane == 0) sc[p] = d + bbp[0];
    }
    __syncthreads();
    if (tid < 32) {
        float v = sc[tid];
        float m = v;
#pragma unroll
        for (int o = 16; o > 0; o >>= 1) m = fmaxf(m, __shfl_xor_sync(0xffffffffu, m, o));
        float e = expf(v - m);
        float s = e;
#pragma unroll
        for (int o = 16; o > 0; o >>= 1) s += __shfl_xor_sync(0xffffffffu, s, o);
        out[b * PPG + tid] = v - m - logf(s);
    }
}

// ---------------- launch ----------------
extern "C" void kernel_launch(void* const* d_in, const int* in_sizes, int n_in,
                              void* d_out, int out_size)
{
    (void)in_sizes; (void)n_in; (void)out_size;
    const float* emb_table = (const float*)d_in[0];
    const float* W_t       = (const float*)d_in[1];
    const float* b_t       = (const float*)d_in[2];
    const float* W_r       = (const float*)d_in[3];
    const float* b_r       = (const float*)d_in[4];
    const float* Wb        = (const float*)d_in[5];
    const float* bb        = (const float*)d_in[6];
    const float* norm      = (const float*)d_in[7];
    const int*   gid       = (const int*)d_in[8];
    const int*   spo       = (const int*)d_in[9];
    const int*   access_   = (const int*)d_in[10];
    const int*   pre       = (const int*)d_in[11];
    const int*   src       = (const int*)d_in[12];
    const int*   dst       = (const int*)d_in[13];
    const int*   etype     = (const int*)d_in[14];
    const int*   pred      = (const int*)d_in[15];
    float* out = (float*)d_out;

    void *p_m, *p_deg, *p_emb, *p_h, *p_h2, *p_xinit;
    cudaGetSymbolAddress(&p_m,     g_m);
    cudaGetSymbolAddress(&p_deg,   g_deg);
    cudaGetSymbolAddress(&p_emb,   g_emb);
    cudaGetSymbolAddress(&p_h,     g_h);
    cudaGetSymbolAddress(&p_h2,    g_h2);
    cudaGetSymbolAddress(&p_xinit, g_xinit);

    const int TPB = 256;
    const int gather_blocks  = (NN * 32) / TPB;        // 16384
    const int scatter_blocks = (EE * 32) / TPB;        // 131072
    const int gemm_blocks    = NN / 128;               // 1024

    // --- init_forward ---
    cudaMemsetAsync(p_m,   0, (size_t)NH * sizeof(float), 0);   // agg0 (chunk 0)
    cudaMemsetAsync(p_deg, 0, (size_t)NN * sizeof(float), 0);
    k_gather<<<gather_blocks, TPB>>>((const float4*)emb_table, gid);
    k_scatter<<<scatter_blocks, TPB>>>((const float4*)p_emb, src, dst, etype, norm, 1);
    k_select_xinit<<<gather_blocks, TPB>>>(spo, access_, pre, W_t, b_t);

    // --- input projection: h0 = emb @ W_t[:128] + xinit ---
    k_gemm<<<gemm_blocks, TPB>>>((const float*)p_emb, 0, W_t, 0, 1,
                                 (const float*)p_xinit, nullptr, nullptr,
                                 (float*)p_h, 0);

    // --- layer 0 ---
    cudaMemsetAsync(p_m, 0, 4ULL * NH * sizeof(float), 0);
    k_scatter<<<scatter_blocks, TPB>>>((const float4*)p_h, src, dst, etype, norm, 0);
    k_gemm<<<gemm_blocks, TPB>>>((const float*)p_m, (long)NH, W_r, (long)(HH * HH), 4,
                                 nullptr, b_r, (const float*)p_h,
                                 (float*)p_h2, 1);

    // --- layer 1 ---
    cudaMemsetAsync(p_m, 0, 4ULL * NH * sizeof(float), 0);
    k_scatter<<<scatter_blocks, TPB>>>((const float4*)p_h2, src, dst, etype, norm, 0);
    k_gemm<<<gemm_blocks, TPB>>>((const float*)p_m, (long)NH, W_r + 4 * HH * HH, (long)(HH * HH), 4,
                                 nullptr, b_r + HH, nullptr,
                                 (float*)p_h, 1);

    // --- head ---
    k_transpose<<<(HH * HH) / TPB, TPB>>>(Wb);
    k_pool<<<BBG, HH>>>((const float*)p_h, pred);
    k_tp<<<BBG, HH>>>();
    k_score<<<BBG, HH>>>((const float*)p_h, pred, bb, out);
}

// round 3
// speedup vs baseline: 1.5847x; 1.5847x over previous
#include <cuda_runtime.h>
#include <cuda_bf16.h>
#include <cstdint>

// Problem constants (fixed by the dataset)
#define NN   131072      // nodes
#define EE   1048576     // edges
#define HH   128         // hidden = emb dim
#define BBG  512         // graphs
#define PPG  32          // predicates per graph
#define NH   (NN*HH)     // floats per [N,H] buffer

// ---------------- static device scratch ----------------
__device__ float g_emb[NH];
__device__ float g_h[NH];
__device__ float g_h2[NH];
__device__ float g_xinit[NH];
__device__ float g_m[4ULL * NH];
__device__ float g_deg[NN];
__device__ float g_pool[BBG * HH];
__device__ float g_tp[BBG * HH];
__device__ float g_wbt[HH * HH];

// ---------------- helpers ----------------
__device__ __forceinline__ uint32_t smem_u32(const void* p) {
    uint32_t a;
    asm("{ .reg .u64 t; cvta.to.shared.u64 t, %1; cvt.u32.u64 %0, t; }" : "=r"(a) : "l"(p));
    return a;
}

__device__ __forceinline__ void ldsm_x4(uint32_t r[4], uint32_t addr) {
    asm volatile("ldmatrix.sync.aligned.m8n8.x4.shared.b16 {%0,%1,%2,%3}, [%4];"
                 : "=r"(r[0]), "=r"(r[1]), "=r"(r[2]), "=r"(r[3]) : "r"(addr));
}
__device__ __forceinline__ void ldsm_x4_t(uint32_t r[4], uint32_t addr) {
    asm volatile("ldmatrix.sync.aligned.m8n8.x4.trans.shared.b16 {%0,%1,%2,%3}, [%4];"
                 : "=r"(r[0]), "=r"(r[1]), "=r"(r[2]), "=r"(r[3]) : "r"(addr));
}
__device__ __forceinline__ void mma_bf16(float* c, const uint32_t a[4], const uint32_t* b) {
    asm volatile(
        "mma.sync.aligned.m16n8k16.row.col.f32.bf16.bf16.f32 "
        "{%0,%1,%2,%3}, {%4,%5,%6,%7}, {%8,%9}, {%0,%1,%2,%3};"
        : "+f"(c[0]), "+f"(c[1]), "+f"(c[2]), "+f"(c[3])
        : "r"(a[0]), "r"(a[1]), "r"(a[2]), "r"(a[3]), "r"(b[0]), "r"(b[1]));
}

__device__ __forceinline__ void split2(float a, float b, uint32_t& hi, uint32_t& lo) {
    __nv_bfloat16 ha = __float2bfloat16_rn(a);
    __nv_bfloat16 hb = __float2bfloat16_rn(b);
    __nv_bfloat16 la = __float2bfloat16_rn(a - __bfloat162float(ha));
    __nv_bfloat16 lb = __float2bfloat16_rn(b - __bfloat162float(hb));
    hi = (uint32_t)__bfloat16_as_ushort(ha) | ((uint32_t)__bfloat16_as_ushort(hb) << 16);
    lo = (uint32_t)__bfloat16_as_ushort(la) | ((uint32_t)__bfloat16_as_ushort(lb) << 16);
}

__device__ __forceinline__ void red_add_v4(float* addr, float x, float y, float z, float w) {
    asm volatile("red.global.add.v4.f32 [%0], {%1,%2,%3,%4};"
                 :: "l"(addr), "f"(x), "f"(y), "f"(z), "f"(w) : "memory");
}

// ---------------- elementwise / graph kernels ----------------

__global__ void k_gather(const float4* __restrict__ tab, const int* __restrict__ gid) {
    int idx = blockIdx.x * blockDim.x + threadIdx.x;
    if (idx >= NN * 32) return;
    int node = idx >> 5;
    int f    = idx & 31;
    ((float4*)g_emb)[idx] = tab[(size_t)gid[node] * 32 + f];
}

__global__ void k_scatter(const float4* __restrict__ hsrc,
                          const int* __restrict__ src, const int* __restrict__ dst,
                          const int* __restrict__ et,  const float* __restrict__ norm,
                          int only_ne)
{
    int gw   = (blockIdx.x * blockDim.x + threadIdx.x) >> 5;
    int lane = threadIdx.x & 31;
    if (gw >= EE) return;
    int t = et[gw];
    if (only_ne && t != 0) return;
    float w = norm[gw];
    int s = src[gw], d = dst[gw];
    float4 v = hsrc[(size_t)s * 32 + lane];
    float* out = g_m + (only_ne ? (size_t)0 : (size_t)t * NH) + (size_t)d * HH + lane * 4;
    red_add_v4(out, v.x * w, v.y * w, v.z * w, v.w * w);
    if (only_ne && lane == 0) atomicAdd(&g_deg[d], 1.0f);
}

__global__ void k_select_xinit(const int* __restrict__ spo, const int* __restrict__ acc,
                               const int* __restrict__ pre, const float* __restrict__ Wt,
                               const float* __restrict__ bt)
{
    int idx = blockIdx.x * blockDim.x + threadIdx.x;
    if (idx >= NN * 32) return;
    int node = idx >> 5;
    int f    = idx & 31;
    int s0 = spo[node * 3 + 0];
    int s1 = spo[node * 3 + 1];
    int s2 = spo[node * 3 + 2];
    if ((s0 + s2) > 0 && g_deg[node] > 0.0f)
        ((float4*)g_emb)[idx] = ((const float4*)g_m)[idx];

    float coef[5];
    coef[0] = (float)s0; coef[1] = (float)s1; coef[2] = (float)s2;
    coef[3] = (float)acc[node]; coef[4] = (float)pre[node];
    float4 r = ((const float4*)bt)[f];
#pragma unroll
    for (int j = 0; j < 5; j++) {
        float4 w = ((const float4*)(Wt + (size_t)(128 + j) * HH))[f];
        r.x += coef[j] * w.x; r.y += coef[j] * w.y;
        r.z += coef[j] * w.z; r.w += coef[j] * w.w;
    }
    ((float4*)g_xinit)[idx] = r;
}

// ---------------- HMMA bf16x3 GEMM ----------------
// C[N,128] = sum over chunks of A[N,128]@B[128,128], K in 64-wide sub-chunks.
// fp32 emulated with bf16 hi/lo split: Ah*Bh + Al*Bh + Ah*Bl.
// smem: A_hi[128][72bf16 rows=144B], A_lo, B_hi[64][136bf16 rows=272B], B_lo

#define SM_AHI 0
#define SM_ALO 18432
#define SM_BHI 36864
#define SM_BLO 54272
#define SM_TOT 71680

__global__ void __launch_bounds__(256, 2) k_gemm_tc(
    const float* __restrict__ A, long strideA,
    const float* __restrict__ B, long strideB, int nkc,
    const float* __restrict__ Cadd, const float* __restrict__ bias,
    const float* __restrict__ resid, float* __restrict__ C, int do_relu)
{
    extern __shared__ char smem[];
    uint32_t s0 = smem_u32(smem);
    int tid = threadIdx.x, wid = tid >> 5, lane = tid & 31;
    int row0 = blockIdx.x * 128;
    int warp_m = wid & 1;        // 0..1 -> 64 rows each
    int warp_n = wid >> 1;       // 0..3 -> 32 cols each

    float c[4][4][4];
#pragma unroll
    for (int i = 0; i < 4; i++)
#pragma unroll
        for (int j = 0; j < 4; j++)
#pragma unroll
            for (int q = 0; q < 4; q++) c[i][j][q] = 0.0f;

    for (int ch = 0; ch < nkc; ch++) {
        // ---- load chunk: A[128][64] fp32, B[64][128] fp32, split to bf16 ----
        if (tid < 128) {
            const float* ga = A + (size_t)(ch >> 1) * strideA
                                + (size_t)row0 * HH + (ch & 1) * 64;
#pragma unroll
            for (int p = 0; p < 16; p++) {
                int e = p * 128 + tid;       // float4 index over 128x16
                int r = e >> 4, c4 = e & 15;
                float4 v = *(const float4*)(ga + (size_t)r * HH + c4 * 4);
                uint32_t h0, l0, h1, l1;
                split2(v.x, v.y, h0, l0);
                split2(v.z, v.w, h1, l1);
                uint32_t off = (uint32_t)r * 144 + c4 * 8;
                *(uint2*)(smem + SM_AHI + off) = make_uint2(h0, h1);
                *(uint2*)(smem + SM_ALO + off) = make_uint2(l0, l1);
            }
        } else {
            int t = tid - 128;
            const float* gb = B + (size_t)(ch >> 1) * strideB
                                + (size_t)((ch & 1) * 64) * HH;
#pragma unroll
            for (int p = 0; p < 16; p++) {
                int e = p * 128 + t;         // float4 index over 64x32
                int k = e >> 5, c4 = e & 31;
                float4 v = *(const float4*)(gb + (size_t)k * HH + c4 * 4);
                uint32_t h0, l0, h1, l1;
                split2(v.x, v.y, h0, l0);
                split2(v.z, v.w, h1, l1);
                uint32_t off = (uint32_t)k * 272 + c4 * 8;
                *(uint2*)(smem + SM_BHI + off) = make_uint2(h0, h1);
                *(uint2*)(smem + SM_BLO + off) = make_uint2(l0, l1);
            }
        }
        __syncthreads();

        // ---- mma over 4 k-steps of 16 ----
#pragma unroll
        for (int ks = 0; ks < 4; ks++) {
            uint32_t ah[4][4], al[4][4];
#pragma unroll
            for (int mt = 0; mt < 4; mt++) {
                uint32_t row  = warp_m * 64 + mt * 16 + (lane & 15);
                uint32_t addr = s0 + SM_AHI + row * 144 + ks * 32 + ((lane >> 4) << 4);
                ldsm_x4(ah[mt], addr);
                ldsm_x4(al[mt], addr + (SM_ALO - SM_AHI));
            }
#pragma unroll
            for (int np = 0; np < 2; np++) {
                uint32_t kk   = ks * 16 + (lane & 15);
                uint32_t col  = warp_n * 32 + np * 16 + ((lane >> 4) & 1) * 8;
                uint32_t addr = s0 + SM_BHI + kk * 272 + col * 2;
                uint32_t bh[4], bl[4];
                ldsm_x4_t(bh, addr);
                ldsm_x4_t(bl, addr + (SM_BLO - SM_BHI));
#pragma unroll
                for (int mt = 0; mt < 4; mt++) {
                    mma_bf16(c[mt][np * 2],     ah[mt], bh);
                    mma_bf16(c[mt][np * 2],     al[mt], bh);
                    mma_bf16(c[mt][np * 2],     ah[mt], bl);
                    mma_bf16(c[mt][np * 2 + 1], ah[mt], bh + 2);
                    mma_bf16(c[mt][np * 2 + 1], al[mt], bh + 2);
                    mma_bf16(c[mt][np * 2 + 1], ah[mt], bl + 2);
                }
            }
        }
        __syncthreads();
    }

    // ---- epilogue: fused Cadd / bias / relu / residual ----
#pragma unroll
    for (int mt = 0; mt < 4; mt++) {
#pragma unroll
        for (int nt = 0; nt < 4; nt++) {
            int col = warp_n * 32 + nt * 8 + (lane & 3) * 2;
            float2 bv = make_float2(0.f, 0.f);
            if (bias) bv = *(const float2*)(bias + col);
#pragma unroll
            for (int half = 0; half < 2; half++) {
                long row  = row0 + warp_m * 64 + mt * 16 + (lane >> 2) + half * 8;
                long base = row * HH + col;
                float2 v;
                v.x = c[mt][nt][half * 2 + 0];
                v.y = c[mt][nt][half * 2 + 1];
                if (Cadd) {
                    float2 t = *(const float2*)(Cadd + base);
                    v.x += t.x; v.y += t.y;
                }
                if (bias) { v.x += bv.x; v.y += bv.y; }
                if (do_relu) { v.x = fmaxf(v.x, 0.f); v.y = fmaxf(v.y, 0.f); }
                if (resid) {
                    float2 t = *(const float2*)(resid + base);
                    v.x += t.x; v.y += t.y;
                }
                *(float2*)(C + base) = v;
            }
        }
    }
}

// ---------------- head kernels ----------------

__global__ void k_transpose(const float* __restrict__ Wb) {
    int idx = blockIdx.x * blockDim.x + threadIdx.x;
    if (idx >= HH * HH) return;
    int r = idx >> 7, c = idx & 127;
    g_wbt[c * HH + r] = Wb[idx];
}

__global__ void k_pool(const float* __restrict__ h, const int* __restrict__ pred) {
    int b = blockIdx.x, j = threadIdx.x;
    float acc = 0.0f;
#pragma unroll 4
    for (int p = 0; p < PPG; p++) {
        int node = pred[b * PPG + p];
        acc += h[(size_t)node * HH + j];
    }
    g_pool[b * HH + j] = acc * (1.0f / PPG);
}

__global__ void k_tp() {
    int b = blockIdx.x, hrow = threadIdx.x;
    __shared__ float ps[HH];
    ps[hrow] = g_pool[b * HH + hrow];
    __syncthreads();
    float acc = 0.0f;
#pragma unroll 8
    for (int k = 0; k < HH; k++)
        acc += g_wbt[(size_t)k * HH + hrow] * ps[k];
    g_tp[b * HH + hrow] = acc;
}

__global__ void k_score(const float* __restrict__ h, const int* __restrict__ pred,
                        const float* __restrict__ bbp, float* __restrict__ out)
{
    int b = blockIdx.x;
    int tid = threadIdx.x;
    __shared__ __align__(16) float tps[HH];
    __shared__ float sc[PPG];
    tps[tid] = g_tp[b * HH + tid];
    __syncthreads();
    int warp = tid >> 5, lane = tid & 31;
    float4 tv = ((const float4*)tps)[lane];
    for (int p = warp; p < PPG; p += 4) {
        int node = pred[b * PPG + p];
        float4 hv = ((const float4*)h)[(size_t)node * 32 + lane];
        float d = hv.x * tv.x + hv.y * tv.y + hv.z * tv.z + hv.w * tv.w;
#pragma unroll
        for (int o = 16; o > 0; o >>= 1) d += __shfl_xor_sync(0xffffffffu, d, o);
        if (lane == 0) sc[p] = d + bbp[0];
    }
    __syncthreads();
    if (tid < 32) {
        float v = sc[tid];
        float m = v;
#pragma unroll
        for (int o = 16; o > 0; o >>= 1) m = fmaxf(m, __shfl_xor_sync(0xffffffffu, m, o));
        float e = expf(v - m);
        float s = e;
#pragma unroll
        for (int o = 16; o > 0; o >>= 1) s += __shfl_xor_sync(0xffffffffu, s, o);
        out[b * PPG + tid] = v - m - logf(s);
    }
}

// ---------------- launch ----------------
extern "C" void kernel_launch(void* const* d_in, const int* in_sizes, int n_in,
                              void* d_out, int out_size)
{
    (void)in_sizes; (void)n_in; (void)out_size;
    const float* emb_table = (const float*)d_in[0];
    const float* W_t       = (const float*)d_in[1];
    const float* b_t       = (const float*)d_in[2];
    const float* W_r       = (const float*)d_in[3];
    const float* b_r       = (const float*)d_in[4];
    const float* Wb        = (const float*)d_in[5];
    const float* bb        = (const float*)d_in[6];
    const float* norm      = (const float*)d_in[7];
    const int*   gid       = (const int*)d_in[8];
    const int*   spo       = (const int*)d_in[9];
    const int*   access_   = (const int*)d_in[10];
    const int*   pre       = (const int*)d_in[11];
    const int*   src       = (const int*)d_in[12];
    const int*   dst       = (const int*)d_in[13];
    const int*   etype     = (const int*)d_in[14];
    const int*   pred      = (const int*)d_in[15];
    float* out = (float*)d_out;

    void *p_m, *p_deg, *p_emb, *p_h, *p_h2, *p_xinit;
    cudaGetSymbolAddress(&p_m,     g_m);
    cudaGetSymbolAddress(&p_deg,   g_deg);
    cudaGetSymbolAddress(&p_emb,   g_emb);
    cudaGetSymbolAddress(&p_h,     g_h);
    cudaGetSymbolAddress(&p_h2,    g_h2);
    cudaGetSymbolAddress(&p_xinit, g_xinit);

    const int TPB = 256;
    const int gather_blocks  = (NN * 32) / TPB;
    const int scatter_blocks = (EE * 32) / TPB;
    const int gemm_blocks    = NN / 128;

    cudaFuncSetAttribute(k_gemm_tc, cudaFuncAttributeMaxDynamicSharedMemorySize, SM_TOT);

    // --- init_forward ---
    cudaMemsetAsync(p_m,   0, (size_t)NH * sizeof(float), 0);
    cudaMemsetAsync(p_deg, 0, (size_t)NN * sizeof(float), 0);
    k_gather<<<gather_blocks, TPB>>>((const float4*)emb_table, gid);
    k_scatter<<<scatter_blocks, TPB>>>((const float4*)p_emb, src, dst, etype, norm, 1);
    k_select_xinit<<<gather_blocks, TPB>>>(spo, access_, pre, W_t, b_t);

    // --- input projection: h0 = emb @ W_t[:128] + xinit ---
    k_gemm_tc<<<gemm_blocks, TPB, SM_TOT>>>(
        (const float*)p_emb, 0, W_t, 0, 2,
        (const float*)p_xinit, nullptr, nullptr, (float*)p_h, 0);

    // --- layer 0 ---
    cudaMemsetAsync(p_m, 0, 4ULL * NH * sizeof(float), 0);
    k_scatter<<<scatter_blocks, TPB>>>((const float4*)p_h, src, dst, etype, norm, 0);
    k_gemm_tc<<<gemm_blocks, TPB, SM_TOT>>>(
        (const float*)p_m, (long)NH, W_r, (long)(HH * HH), 8,
        nullptr, b_r, (const float*)p_h, (float*)p_h2, 1);

    // --- layer 1 ---
    cudaMemsetAsync(p_m, 0, 4ULL * NH * sizeof(float), 0);
    k_scatter<<<scatter_blocks, TPB>>>((const float4*)p_h2, src, dst, etype, norm, 0);
    k_gemm_tc<<<gemm_blocks, TPB, SM_TOT>>>(
        (const float*)p_m, (long)NH, W_r + 4 * HH * HH, (long)(HH * HH), 8,
        nullptr, b_r + HH, nullptr, (float*)p_h, 1);

    // --- head ---
    k_transpose<<<(HH * HH) / TPB, TPB>>>(Wb);
    k_pool<<<BBG, HH>>>((const float*)p_h, pred);
    k_tp<<<BBG, HH>>>();
    k_score<<<BBG, HH>>>((const float*)p_h, pred, bb, out);
}